// round 7
// baseline (speedup 1.0000x reference)
#include <cuda_runtime.h>

// Net_multi_11390253269716: 3-level GCN U-Net, 784x480 grid, C=32.
// R7: R3 build+gemm pipeline (proven 248us) + warp-per-node gathers
//     (4 concurrent edge slots, xor-reduce) to kill degree imbalance.

#define NXg 784
#define NYg 480
#define C 32
#define N0 (NXg * NYg)        // 376320
#define N1 (N0 / 4)           // 94080
#define N2 (N0 / 16)          // 23520
#define E0 (4 * N0)
#define E1 (4 * N1)
#define E2 (4 * N2)
#define ETOT (E0 + E1 + E2)   // 1975680
#define M (N0 + N1 + N2)      // 493920
#define GB1 N0
#define GB2 (N0 + N1)
#define SCAN_NBLK ((M + 1023) / 1024)   // 483

typedef unsigned long long ull;

// ---------------- scratch ----------------
__device__ float4 g_Y [N0 * 8];   // x@w temp (levels reuse prefix)
__device__ float4 g_H [N0 * 8];   // GCN1 out (pre-relu)
__device__ float4 g_G2[N1 * 8];
__device__ float4 g_G4[N1 * 8];
__device__ float4 g_G3[N2 * 8];
__device__ int   g_cnt[M];
__device__ int   g_rowptr[M + 1];
__device__ int   g_eix[ETOT];
__device__ float g_dinv[M];
__device__ int   g_bsum[SCAN_NBLK];

// ---------------- f32x2 helpers ----------------
__device__ __forceinline__ ull pk2(float a, float b) {
    ull r; asm("mov.b64 %0, {%1, %2};" : "=l"(r) : "f"(a), "f"(b)); return r;
}
__device__ __forceinline__ ull fma2_(ull a, ull b, ull c) {
    ull d; asm("fma.rn.f32x2 %0, %1, %2, %3;" : "=l"(d) : "l"(a), "l"(b), "l"(c)); return d;
}
__device__ __forceinline__ ull add2_(ull a, ull b) {
    ull d; asm("add.rn.f32x2 %0, %1, %2;" : "=l"(d) : "l"(a), "l"(b)); return d;
}
__device__ __forceinline__ float2 up2_(ull v) {
    float2 f; asm("mov.b64 {%0, %1}, %2;" : "=f"(f.x), "=f"(f.y) : "l"(v)); return f;
}
__device__ __forceinline__ float4 relu4(float4 v) {
    v.x = fmaxf(v.x, 0.f); v.y = fmaxf(v.y, 0.f);
    v.z = fmaxf(v.z, 0.f); v.w = fmaxf(v.w, 0.f);
    return v;
}

// ---------------- CSR build (R3-proven, 6 launches) ----------------
__global__ void zero_cnt() {
    int i = blockIdx.x * blockDim.x + threadIdx.x;
    if (i < M) g_cnt[i] = 0;
}

__global__ void hist3(const int* __restrict__ d0, const int* __restrict__ d1,
                      const int* __restrict__ d2) {
    int t = blockIdx.x * blockDim.x + threadIdx.x;
    int g;
    if (t < E0) g = d0[t];
    else if (t < E0 + E1) g = GB1 + d1[t - E0];
    else if (t < ETOT) g = GB2 + d2[t - E0 - E1];
    else return;
    atomicAdd(&g_cnt[g], 1);
}

__global__ void scanA() {
    __shared__ int sb[256];
    int tid = threadIdx.x;
    int base = blockIdx.x * 1024 + tid * 4;
    int v = 0;
    #pragma unroll
    for (int k = 0; k < 4; k++) if (base + k < M) v += g_cnt[base + k];
    sb[tid] = v; __syncthreads();
    for (int off = 128; off; off >>= 1) {
        if (tid < off) sb[tid] += sb[tid + off];
        __syncthreads();
    }
    if (tid == 0) g_bsum[blockIdx.x] = sb[0];
}

__global__ void scanB() {
    __shared__ int sb[512];
    int tid = threadIdx.x;
    int v = (tid < SCAN_NBLK) ? g_bsum[tid] : 0;
    sb[tid] = v; __syncthreads();
    for (int off = 1; off < 512; off <<= 1) {
        int t = (tid >= off) ? sb[tid - off] : 0;
        __syncthreads();
        sb[tid] += t;
        __syncthreads();
    }
    if (tid < SCAN_NBLK) g_bsum[tid] = sb[tid] - v;
}

__global__ void scanC() {
    __shared__ int sb[256];
    int tid = threadIdx.x;
    int base = blockIdx.x * 1024 + tid * 4;
    int v[4], p[4], tsum = 0;
    #pragma unroll
    for (int k = 0; k < 4; k++) {
        v[k] = (base + k < M) ? g_cnt[base + k] : 0;
        p[k] = tsum; tsum += v[k];
    }
    sb[tid] = tsum; __syncthreads();
    for (int off = 1; off < 256; off <<= 1) {
        int t = (tid >= off) ? sb[tid - off] : 0;
        __syncthreads();
        sb[tid] += t;
        __syncthreads();
    }
    int off0 = g_bsum[blockIdx.x] + sb[tid] - tsum;
    #pragma unroll
    for (int k = 0; k < 4; k++) {
        int i = base + k;
        if (i < M) {
            g_rowptr[i] = off0 + p[k];
            g_dinv[i] = rsqrtf((float)v[k] + 1.0f);
            g_cnt[i] = 0;
        }
    }
    if (blockIdx.x == 0 && tid == 0) g_rowptr[M] = ETOT;
}

__global__ void fill3(const int* __restrict__ ei0, const int* __restrict__ ei1,
                      const int* __restrict__ ei2) {
    int t = blockIdx.x * blockDim.x + threadIdx.x;
    int g, s;
    if (t < E0)           { g = ei0[E0 + t];                 s = ei0[t]; }
    else if (t < E0 + E1) { int e = t - E0;      g = GB1 + ei1[E1 + e]; s = ei1[e]; }
    else if (t < ETOT)    { int e = t - E0 - E1; g = GB2 + ei2[E2 + e]; s = ei2[e]; }
    else return;
    int pos = g_rowptr[g] + atomicAdd(&g_cnt[g], 1);
    g_eix[pos] = s;
}

// ---------------- gemm: 8 thr/node, 4 nodes/group, f32x2 ----------------
#define GEMM_PROLOG(n_)                                                   \
    __shared__ ulonglong2 swu[256];                                       \
    int tid = threadIdx.x;                                                \
    swu[tid] = ((const ulonglong2*)w)[tid];                               \
    int sub = tid & 7;                                                    \
    int nb = (blockIdx.x * 32 + (tid >> 3)) * 4;                          \
    float4 xq[4];

#define GEMM_BODY(n_)                                                     \
    __syncthreads();                                                      \
    ull a01[4] = {0, 0, 0, 0}, a23[4] = {0, 0, 0, 0};                     \
    _Pragma("unroll")                                                     \
    for (int g = 0; g < 8; g++) {                                         \
        ulonglong2 w0 = swu[(4 * g + 0) * 8 + sub];                       \
        ulonglong2 w1 = swu[(4 * g + 1) * 8 + sub];                       \
        ulonglong2 w2 = swu[(4 * g + 2) * 8 + sub];                       \
        ulonglong2 w3 = swu[(4 * g + 3) * 8 + sub];                       \
        _Pragma("unroll")                                                 \
        for (int j = 0; j < 4; j++) {                                     \
            float x0 = __shfl_sync(0xffffffffu, xq[j].x, g, 8);           \
            float x1 = __shfl_sync(0xffffffffu, xq[j].y, g, 8);           \
            float x2 = __shfl_sync(0xffffffffu, xq[j].z, g, 8);           \
            float x3 = __shfl_sync(0xffffffffu, xq[j].w, g, 8);           \
            a01[j] = fma2_(pk2(x0, x0), w0.x, a01[j]);                    \
            a23[j] = fma2_(pk2(x0, x0), w0.y, a23[j]);                    \
            a01[j] = fma2_(pk2(x1, x1), w1.x, a01[j]);                    \
            a23[j] = fma2_(pk2(x1, x1), w1.y, a23[j]);                    \
            a01[j] = fma2_(pk2(x2, x2), w2.x, a01[j]);                    \
            a23[j] = fma2_(pk2(x2, x2), w2.y, a23[j]);                    \
            a01[j] = fma2_(pk2(x3, x3), w3.x, a01[j]);                    \
            a23[j] = fma2_(pk2(x3, x3), w3.y, a23[j]);                    \
        }                                                                 \
    }                                                                     \
    _Pragma("unroll")                                                     \
    for (int j = 0; j < 4; j++)                                           \
        if (nb + j < n_) {                                                \
            ulonglong2 r; r.x = a01[j]; r.y = a23[j];                     \
            ((ulonglong2*)Y)[(nb + j) * 8 + sub] = r;                     \
        }

__global__ void gemm_fc1(const float4* __restrict__ x,
                         const float* __restrict__ fc1w, const float* __restrict__ fc1b,
                         const float* __restrict__ w,
                         float4* __restrict__ Y, int n)
{
    GEMM_PROLOG(n)
    __shared__ float4 sfw[32];
    __shared__ float4 sfb[8];
    if (tid < 32) sfw[tid] = ((const float4*)fc1w)[tid];
    if (tid < 8)  sfb[tid] = ((const float4*)fc1b)[tid];
    __syncthreads();
    float4 r0 = sfw[0 * 8 + sub], r1 = sfw[1 * 8 + sub];
    float4 r2 = sfw[2 * 8 + sub], r3 = sfw[3 * 8 + sub];
    float4 bb = sfb[sub];
    #pragma unroll
    for (int j = 0; j < 4; j++) {
        float4 xr = (nb + j < n) ? x[nb + j] : make_float4(0.f, 0.f, 0.f, 0.f);
        float4 h = bb;
        h.x += xr.x * r0.x + xr.y * r1.x + xr.z * r2.x + xr.w * r3.x;
        h.y += xr.x * r0.y + xr.y * r1.y + xr.z * r2.y + xr.w * r3.y;
        h.z += xr.x * r0.z + xr.y * r1.z + xr.z * r2.z + xr.w * r3.z;
        h.w += xr.x * r0.w + xr.y * r1.w + xr.z * r2.w + xr.w * r3.w;
        xq[j] = relu4(h);
    }
    GEMM_BODY(n)
}

__global__ void gemm_down(const float4* __restrict__ in,
                          const float* __restrict__ w,
                          float4* __restrict__ Y, int n, int hy, int win)
{
    GEMM_PROLOG(n)
    #pragma unroll
    for (int j = 0; j < 4; j++) {
        int node = nb + j;
        if (node < n) {
            int ix = node / hy, iy = node - ix * hy;
            int sn = (2 * ix) * win + 2 * iy;
            xq[j] = relu4(in[sn * 8 + sub]);
        } else xq[j] = make_float4(0.f, 0.f, 0.f, 0.f);
    }
    GEMM_BODY(n)
}

__global__ void gemm_upadd(const float4* __restrict__ base,
                           const float4* __restrict__ coarse,
                           const float* __restrict__ w,
                           float4* __restrict__ Y, int n, int hy)
{
    GEMM_PROLOG(n)
    #pragma unroll
    for (int j = 0; j < 4; j++) {
        int node = nb + j;
        if (node < n) {
            int ix = node / hy, iy = node - ix * hy;
            int cn = (ix >> 1) * (hy >> 1) + (iy >> 1);
            float4 xb = relu4(base[node * 8 + sub]);
            float4 xc = relu4(coarse[cn * 8 + sub]);
            xq[j] = make_float4(xb.x + xc.x, xb.y + xc.y, xb.z + xc.z, xb.w + xc.w);
        } else xq[j] = make_float4(0.f, 0.f, 0.f, 0.f);
    }
    GEMM_BODY(n)
}

// ---------------- warp-per-node gather ----------------
// 32 lanes = 8 subs (channel quads) x 4 edge slots; slots process edges
// concurrently, then xor-reduce (8, 16). All lanes end with the row chunk
// for their sub.
__device__ __forceinline__ float4 gcn_row_warp(const ulonglong2* __restrict__ Yp,
                                               int node, int sub, int eslot,
                                               int gb, const float* __restrict__ bias)
{
    int beg = g_rowptr[gb + node];
    int end = g_rowptr[gb + node + 1];
    float dd = g_dinv[gb + node];
    ull a01 = 0, a23 = 0;
    for (int p = beg + eslot; p < end; p += 4) {
        int s = g_eix[p];
        float nm = g_dinv[gb + s];
        ulonglong2 v = Yp[s * 8 + sub];
        ull nn = pk2(nm, nm);
        a01 = fma2_(v.x, nn, a01);
        a23 = fma2_(v.y, nn, a23);
    }
    a01 = add2_(a01, __shfl_xor_sync(0xffffffffu, a01, 8));
    a23 = add2_(a23, __shfl_xor_sync(0xffffffffu, a23, 8));
    a01 = add2_(a01, __shfl_xor_sync(0xffffffffu, a01, 16));
    a23 = add2_(a23, __shfl_xor_sync(0xffffffffu, a23, 16));
    ulonglong2 self = Yp[node * 8 + sub];
    ull ddp = pk2(dd, dd);
    ull t01 = fma2_(self.x, ddp, a01);
    ull t23 = fma2_(self.y, ddp, a23);
    float4 bb = ((const float4*)bias)[sub];
    float2 q01 = up2_(fma2_(t01, ddp, pk2(bb.x, bb.y)));
    float2 q23 = up2_(fma2_(t23, ddp, pk2(bb.z, bb.w)));
    return make_float4(q01.x, q01.y, q23.x, q23.y);
}

__global__ void gather(const float4* __restrict__ Yf,
                       const float* __restrict__ bias,
                       float4* __restrict__ OUT, int n, int gb)
{
    int node = (blockIdx.x * blockDim.x + threadIdx.x) >> 5;
    if (node >= n) return;
    int lane = threadIdx.x & 31;
    int sub = lane & 7, eslot = lane >> 3;
    float4 row = gcn_row_warp((const ulonglong2*)Yf, node, sub, eslot, gb, bias);
    if (eslot == 0) OUT[node * 8 + sub] = row;
}

__global__ void gather_fc2(const float4* __restrict__ Yf,
                           const float* __restrict__ bias,
                           const float* __restrict__ w2, const float* __restrict__ b2,
                           float* __restrict__ out, int n)
{
    __shared__ float sw[96];
    int tid = threadIdx.x;
    if (tid < 96) sw[tid] = w2[tid];
    __syncthreads();
    int node = (blockIdx.x * blockDim.x + tid) >> 5;
    if (node >= n) return;
    int lane = tid & 31;
    int sub = lane & 7, eslot = lane >> 3;
    float4 v = relu4(gcn_row_warp((const ulonglong2*)Yf, node, sub, eslot, 0, bias));
    int c = 4 * sub;
    float p0 = v.x * sw[(c+0)*3+0] + v.y * sw[(c+1)*3+0] + v.z * sw[(c+2)*3+0] + v.w * sw[(c+3)*3+0];
    float p1 = v.x * sw[(c+0)*3+1] + v.y * sw[(c+1)*3+1] + v.z * sw[(c+2)*3+1] + v.w * sw[(c+3)*3+1];
    float p2 = v.x * sw[(c+0)*3+2] + v.y * sw[(c+1)*3+2] + v.z * sw[(c+2)*3+2] + v.w * sw[(c+3)*3+2];
    #pragma unroll
    for (int off = 4; off; off >>= 1) {
        p0 += __shfl_down_sync(0xffffffffu, p0, off, 8);
        p1 += __shfl_down_sync(0xffffffffu, p1, off, 8);
        p2 += __shfl_down_sync(0xffffffffu, p2, off, 8);
    }
    if (lane == 0) {
        out[node * 3 + 0] = p0 + __ldg(&b2[0]);
        out[node * 3 + 1] = p1 + __ldg(&b2[1]);
        out[node * 3 + 2] = p2 + __ldg(&b2[2]);
    }
}

// ---------------------------------------------------------------------------
static inline int ceil_div(int a, int b) { return (a + b - 1) / b; }

extern "C" void kernel_launch(void* const* d_in, const int* in_sizes, int n_in,
                              void* d_out, int out_size) {
    const float* x     = (const float*)d_in[0];
    const float* fc1_w = (const float*)d_in[1];
    const float* fc1_b = (const float*)d_in[2];
    const float* w1 = (const float*)d_in[3];  const float* b1 = (const float*)d_in[4];
    const float* w2 = (const float*)d_in[5];  const float* b2 = (const float*)d_in[6];
    const float* w3 = (const float*)d_in[7];  const float* b3 = (const float*)d_in[8];
    const float* w4 = (const float*)d_in[9];  const float* b4 = (const float*)d_in[10];
    const float* w5 = (const float*)d_in[11]; const float* b5 = (const float*)d_in[12];
    const float* fc2_w = (const float*)d_in[13];
    const float* fc2_b = (const float*)d_in[14];
    const int* ei0 = (const int*)d_in[18];
    const int* ei1 = (const int*)d_in[19];
    const int* ei2 = (const int*)d_in[20];
    float* out = (float*)d_out;

    float4 *Y, *H, *G2, *G4, *G3;
    cudaGetSymbolAddress((void**)&Y,  g_Y);
    cudaGetSymbolAddress((void**)&H,  g_H);
    cudaGetSymbolAddress((void**)&G2, g_G2);
    cudaGetSymbolAddress((void**)&G4, g_G4);
    cudaGetSymbolAddress((void**)&G3, g_G3);

    const int TB = 256;

    // 0-2: start of CSR build
    zero_cnt<<<ceil_div(M, TB), TB>>>();
    hist3<<<ceil_div(ETOT, TB), TB>>>(ei0 + E0, ei1 + E1, ei2 + E2);
    scanA<<<SCAN_NBLK, 256>>>();
    // 3: GCN1 gemm (CSR-independent; placed here so ncu's 4th-launch capture
    //    profiles it next round)
    gemm_fc1<<<ceil_div(N0, 128), TB>>>((const float4*)x, fc1_w, fc1_b, w1, Y, N0);
    // 4-6: rest of CSR build
    scanB<<<1, 512>>>();
    scanC<<<SCAN_NBLK, 256>>>();
    fill3<<<ceil_div(ETOT, TB), TB>>>(ei0, ei1, ei2);

    // 7: GCN1 gather (warp-per-node)
    gather<<<ceil_div(N0, 8), TB>>>(Y, b1, H, N0, 0);

    // 8-9: GCN2
    gemm_down<<<ceil_div(N1, 128), TB>>>(H, w2, Y, N1, NYg / 2, NYg);
    gather<<<ceil_div(N1, 8), TB>>>(Y, b2, G2, N1, GB1);

    // 10-11: GCN3
    gemm_down<<<ceil_div(N2, 128), TB>>>(G2, w3, Y, N2, NYg / 4, NYg / 2);
    gather<<<ceil_div(N2, 8), TB>>>(Y, b3, G3, N2, GB2);

    // 12-13: GCN4
    gemm_upadd<<<ceil_div(N1, 128), TB>>>(G2, G3, w4, Y, N1, NYg / 2);
    gather<<<ceil_div(N1, 8), TB>>>(Y, b4, G4, N1, GB1);

    // 14-15: GCN5 + fc2
    gemm_upadd<<<ceil_div(N0, 128), TB>>>(H, G4, w5, Y, N0, NYg);
    gather_fc2<<<ceil_div(N0, 8), TB>>>(Y, b5, fc2_w, fc2_b, out, N0);

    (void)in_sizes; (void)n_in; (void)out_size;
}

// round 8
// speedup vs baseline: 1.2901x; 1.2901x over previous
#include <cuda_runtime.h>

// Net_multi_11390253269716: 3-level GCN U-Net, 784x480 grid, C=32.
// R8: thread-per-node gemm (no shuffles; broadcast LDS weights),
//     fused-range pair gather (dense 4-edge batches over 2 nodes),
//     R3-proven 6-launch CSR build.

#define NXg 784
#define NYg 480
#define C 32
#define N0 (NXg * NYg)        // 376320
#define N1 (N0 / 4)           // 94080
#define N2 (N0 / 16)          // 23520
#define E0 (4 * N0)
#define E1 (4 * N1)
#define E2 (4 * N2)
#define ETOT (E0 + E1 + E2)   // 1975680
#define M (N0 + N1 + N2)      // 493920
#define GB1 N0
#define GB2 (N0 + N1)
#define SCAN_NBLK ((M + 1023) / 1024)   // 483

typedef unsigned long long ull;

// ---------------- scratch ----------------
__device__ float4 g_Y [N0 * 8];
__device__ float4 g_H [N0 * 8];
__device__ float4 g_G2[N1 * 8];
__device__ float4 g_G4[N1 * 8];
__device__ float4 g_G3[N2 * 8];
__device__ int   g_cnt[M];
__device__ int   g_rowptr[M + 1];
__device__ int   g_eix[ETOT];
__device__ float g_dinv[M];
__device__ int   g_bsum[SCAN_NBLK];

// ---------------- f32x2 helpers ----------------
__device__ __forceinline__ ull pk2(float a, float b) {
    ull r; asm("mov.b64 %0, {%1, %2};" : "=l"(r) : "f"(a), "f"(b)); return r;
}
__device__ __forceinline__ ull fma2_(ull a, ull b, ull c) {
    ull d; asm("fma.rn.f32x2 %0, %1, %2, %3;" : "=l"(d) : "l"(a), "l"(b), "l"(c)); return d;
}
__device__ __forceinline__ float2 up2_(ull v) {
    float2 f; asm("mov.b64 {%0, %1}, %2;" : "=f"(f.x), "=f"(f.y) : "l"(v)); return f;
}
__device__ __forceinline__ float4 relu4(float4 v) {
    v.x = fmaxf(v.x, 0.f); v.y = fmaxf(v.y, 0.f);
    v.z = fmaxf(v.z, 0.f); v.w = fmaxf(v.w, 0.f);
    return v;
}

// ---------------- CSR build (R3-proven) ----------------
__global__ void zero_cnt() {
    int i = blockIdx.x * blockDim.x + threadIdx.x;
    if (i < M) g_cnt[i] = 0;
}

__global__ void hist3(const int* __restrict__ d0, const int* __restrict__ d1,
                      const int* __restrict__ d2) {
    int t = blockIdx.x * blockDim.x + threadIdx.x;
    int g;
    if (t < E0) g = d0[t];
    else if (t < E0 + E1) g = GB1 + d1[t - E0];
    else if (t < ETOT) g = GB2 + d2[t - E0 - E1];
    else return;
    atomicAdd(&g_cnt[g], 1);
}

__global__ void scanA() {
    __shared__ int sb[256];
    int tid = threadIdx.x;
    int base = blockIdx.x * 1024 + tid * 4;
    int v = 0;
    #pragma unroll
    for (int k = 0; k < 4; k++) if (base + k < M) v += g_cnt[base + k];
    sb[tid] = v; __syncthreads();
    for (int off = 128; off; off >>= 1) {
        if (tid < off) sb[tid] += sb[tid + off];
        __syncthreads();
    }
    if (tid == 0) g_bsum[blockIdx.x] = sb[0];
}

__global__ void scanB() {
    __shared__ int sb[512];
    int tid = threadIdx.x;
    int v = (tid < SCAN_NBLK) ? g_bsum[tid] : 0;
    sb[tid] = v; __syncthreads();
    for (int off = 1; off < 512; off <<= 1) {
        int t = (tid >= off) ? sb[tid - off] : 0;
        __syncthreads();
        sb[tid] += t;
        __syncthreads();
    }
    if (tid < SCAN_NBLK) g_bsum[tid] = sb[tid] - v;
}

__global__ void scanC() {
    __shared__ int sb[256];
    int tid = threadIdx.x;
    int base = blockIdx.x * 1024 + tid * 4;
    int v[4], p[4], tsum = 0;
    #pragma unroll
    for (int k = 0; k < 4; k++) {
        v[k] = (base + k < M) ? g_cnt[base + k] : 0;
        p[k] = tsum; tsum += v[k];
    }
    sb[tid] = tsum; __syncthreads();
    for (int off = 1; off < 256; off <<= 1) {
        int t = (tid >= off) ? sb[tid - off] : 0;
        __syncthreads();
        sb[tid] += t;
        __syncthreads();
    }
    int off0 = g_bsum[blockIdx.x] + sb[tid] - tsum;
    #pragma unroll
    for (int k = 0; k < 4; k++) {
        int i = base + k;
        if (i < M) {
            g_rowptr[i] = off0 + p[k];
            g_dinv[i] = rsqrtf((float)v[k] + 1.0f);
            g_cnt[i] = 0;
        }
    }
    if (blockIdx.x == 0 && tid == 0) g_rowptr[M] = ETOT;
}

__global__ void fill3(const int* __restrict__ ei0, const int* __restrict__ ei1,
                      const int* __restrict__ ei2) {
    int t = blockIdx.x * blockDim.x + threadIdx.x;
    int g, s;
    if (t < E0)           { g = ei0[E0 + t];                 s = ei0[t]; }
    else if (t < E0 + E1) { int e = t - E0;      g = GB1 + ei1[E1 + e]; s = ei1[e]; }
    else if (t < ETOT)    { int e = t - E0 - E1; g = GB2 + ei2[E2 + e]; s = ei2[e]; }
    else return;
    int pos = g_rowptr[g] + atomicAdd(&g_cnt[g], 1);
    g_eix[pos] = s;
}

// ---------------- thread-per-node gemm core (no shuffles) ----------------
// xr[8] = node's 32 input values in registers. Weights broadcast from shared.
#define XK(k) ((k & 3) == 0 ? xr[(k) >> 2].x : (k & 3) == 1 ? xr[(k) >> 2].y \
             : (k & 3) == 2 ? xr[(k) >> 2].z : xr[(k) >> 2].w)

__device__ __forceinline__ void node_gemm(const ulonglong2* swu, const float4* xr,
                                          int node, float4* __restrict__ Y) {
    ull acc[16];
    #pragma unroll
    for (int i = 0; i < 16; i++) acc[i] = 0;
    #pragma unroll
    for (int k = 0; k < 32; k++) {
        float xk = XK(k);
        ull xp = pk2(xk, xk);
        #pragma unroll
        for (int q = 0; q < 8; q++) {
            ulonglong2 wv = swu[k * 8 + q];   // all lanes same addr: broadcast
            acc[2 * q]     = fma2_(xp, wv.x, acc[2 * q]);
            acc[2 * q + 1] = fma2_(xp, wv.y, acc[2 * q + 1]);
        }
    }
    ulonglong2* Yo = (ulonglong2*)(Y + node * 8);
    #pragma unroll
    for (int q = 0; q < 8; q++) {
        ulonglong2 r; r.x = acc[2 * q]; r.y = acc[2 * q + 1];
        Yo[q] = r;
    }
}

__global__ void __launch_bounds__(256)
gemm_fc1(const float4* __restrict__ x,
         const float* __restrict__ fc1w, const float* __restrict__ fc1b,
         const float* __restrict__ w, float4* __restrict__ Y, int n)
{
    __shared__ ulonglong2 swu[256];
    __shared__ float4 sfw[32];
    __shared__ float4 sfb[8];
    int tid = threadIdx.x;
    swu[tid] = ((const ulonglong2*)w)[tid];
    if (tid < 32) sfw[tid] = ((const float4*)fc1w)[tid];
    if (tid < 8)  sfb[tid] = ((const float4*)fc1b)[tid];
    __syncthreads();
    int node = blockIdx.x * 256 + tid;
    if (node >= n) return;
    float4 xin = x[node];
    float4 xr[8];
    #pragma unroll
    for (int q = 0; q < 8; q++) {
        float4 h = sfb[q];
        float4 r0 = sfw[q], r1 = sfw[8 + q], r2 = sfw[16 + q], r3 = sfw[24 + q];
        h.x += xin.x * r0.x + xin.y * r1.x + xin.z * r2.x + xin.w * r3.x;
        h.y += xin.x * r0.y + xin.y * r1.y + xin.z * r2.y + xin.w * r3.y;
        h.z += xin.x * r0.z + xin.y * r1.z + xin.z * r2.z + xin.w * r3.z;
        h.w += xin.x * r0.w + xin.y * r1.w + xin.z * r2.w + xin.w * r3.w;
        xr[q] = relu4(h);
    }
    node_gemm(swu, xr, node, Y);
}

__global__ void __launch_bounds__(256)
gemm_down(const float4* __restrict__ in, const float* __restrict__ w,
          float4* __restrict__ Y, int n, int hy, int win)
{
    __shared__ ulonglong2 swu[256];
    int tid = threadIdx.x;
    swu[tid] = ((const ulonglong2*)w)[tid];
    __syncthreads();
    int node = blockIdx.x * 256 + tid;
    if (node >= n) return;
    int ix = node / hy, iy = node - ix * hy;
    const float4* src = in + ((2 * ix) * win + 2 * iy) * 8;
    float4 xr[8];
    #pragma unroll
    for (int q = 0; q < 8; q++) xr[q] = relu4(src[q]);
    node_gemm(swu, xr, node, Y);
}

__global__ void __launch_bounds__(256)
gemm_upadd(const float4* __restrict__ base, const float4* __restrict__ coarse,
           const float* __restrict__ w, float4* __restrict__ Y, int n, int hy)
{
    __shared__ ulonglong2 swu[256];
    int tid = threadIdx.x;
    swu[tid] = ((const ulonglong2*)w)[tid];
    __syncthreads();
    int node = blockIdx.x * 256 + tid;
    if (node >= n) return;
    int ix = node / hy, iy = node - ix * hy;
    int cn = (ix >> 1) * (hy >> 1) + (iy >> 1);
    const float4* bsrc = base + node * 8;
    const float4* csrc = coarse + cn * 8;
    float4 xr[8];
    #pragma unroll
    for (int q = 0; q < 8; q++) {
        float4 xb = relu4(bsrc[q]);
        float4 xc = relu4(csrc[q]);
        xr[q] = make_float4(xb.x + xc.x, xb.y + xc.y, xb.z + xc.z, xb.w + xc.w);
    }
    node_gemm(swu, xr, node, Y);
}

// ---------------- fused-range pair gather ----------------
// Nodes n0, n0+1 have contiguous CSR ranges [b0,e0) and [e0,e1). Process the
// combined range densely; select-mask the norm into per-node accumulators.
__device__ __forceinline__ void gcn_pair(const ulonglong2* __restrict__ Yp,
                                         int n0, int sub, int gb,
                                         const float* __restrict__ bias,
                                         float4& out0, float4& out1)
{
    int b0 = g_rowptr[gb + n0];
    int e0 = g_rowptr[gb + n0 + 1];
    int e1 = g_rowptr[gb + n0 + 2];
    ull a01 = 0, a23 = 0, c01 = 0, c23 = 0;
    int p = b0;
    for (; p + 4 <= e1; p += 4) {
        int s0 = g_eix[p], s1 = g_eix[p + 1], s2 = g_eix[p + 2], s3 = g_eix[p + 3];
        float m0 = g_dinv[gb + s0], m1 = g_dinv[gb + s1];
        float m2 = g_dinv[gb + s2], m3 = g_dinv[gb + s3];
        ulonglong2 v0 = Yp[s0 * 8 + sub];
        ulonglong2 v1 = Yp[s1 * 8 + sub];
        ulonglong2 v2 = Yp[s2 * 8 + sub];
        ulonglong2 v3 = Yp[s3 * 8 + sub];
        float f0 = (p + 0 < e0) ? m0 : 0.f, g0 = m0 - f0;
        float f1 = (p + 1 < e0) ? m1 : 0.f, g1 = m1 - f1;
        float f2 = (p + 2 < e0) ? m2 : 0.f, g2 = m2 - f2;
        float f3 = (p + 3 < e0) ? m3 : 0.f, g3 = m3 - f3;
        a01 = fma2_(v0.x, pk2(f0, f0), a01); c01 = fma2_(v0.x, pk2(g0, g0), c01);
        a23 = fma2_(v0.y, pk2(f0, f0), a23); c23 = fma2_(v0.y, pk2(g0, g0), c23);
        a01 = fma2_(v1.x, pk2(f1, f1), a01); c01 = fma2_(v1.x, pk2(g1, g1), c01);
        a23 = fma2_(v1.y, pk2(f1, f1), a23); c23 = fma2_(v1.y, pk2(g1, g1), c23);
        a01 = fma2_(v2.x, pk2(f2, f2), a01); c01 = fma2_(v2.x, pk2(g2, g2), c01);
        a23 = fma2_(v2.y, pk2(f2, f2), a23); c23 = fma2_(v2.y, pk2(g2, g2), c23);
        a01 = fma2_(v3.x, pk2(f3, f3), a01); c01 = fma2_(v3.x, pk2(g3, g3), c01);
        a23 = fma2_(v3.y, pk2(f3, f3), a23); c23 = fma2_(v3.y, pk2(g3, g3), c23);
    }
    for (; p < e1; p++) {
        int s = g_eix[p];
        float m = g_dinv[gb + s];
        ulonglong2 v = Yp[s * 8 + sub];
        float f = (p < e0) ? m : 0.f, g = m - f;
        a01 = fma2_(v.x, pk2(f, f), a01); c01 = fma2_(v.x, pk2(g, g), c01);
        a23 = fma2_(v.y, pk2(f, f), a23); c23 = fma2_(v.y, pk2(g, g), c23);
    }
    float dd0 = g_dinv[gb + n0], dd1 = g_dinv[gb + n0 + 1];
    ulonglong2 s0 = Yp[n0 * 8 + sub];
    ulonglong2 s1 = Yp[(n0 + 1) * 8 + sub];
    float4 bb = ((const float4*)bias)[sub];
    ull d0 = pk2(dd0, dd0), d1 = pk2(dd1, dd1);
    float2 q01 = up2_(fma2_(fma2_(s0.x, d0, a01), d0, pk2(bb.x, bb.y)));
    float2 q23 = up2_(fma2_(fma2_(s0.y, d0, a23), d0, pk2(bb.z, bb.w)));
    float2 r01 = up2_(fma2_(fma2_(s1.x, d1, c01), d1, pk2(bb.x, bb.y)));
    float2 r23 = up2_(fma2_(fma2_(s1.y, d1, c23), d1, pk2(bb.z, bb.w)));
    out0 = make_float4(q01.x, q01.y, q23.x, q23.y);
    out1 = make_float4(r01.x, r01.y, r23.x, r23.y);
}

__global__ void gather(const float4* __restrict__ Yf,
                       const float* __restrict__ bias,
                       float4* __restrict__ OUT, int n, int gb)
{
    int t = blockIdx.x * blockDim.x + threadIdx.x;
    int pr = t >> 3, sub = t & 7;
    if (pr >= n / 2) return;
    float4 r0, r1;
    gcn_pair((const ulonglong2*)Yf, pr * 2, sub, gb, bias, r0, r1);
    OUT[(pr * 2) * 8 + sub] = r0;
    OUT[(pr * 2 + 1) * 8 + sub] = r1;
}

__global__ void gather_fc2(const float4* __restrict__ Yf,
                           const float* __restrict__ bias,
                           const float* __restrict__ w2, const float* __restrict__ b2,
                           float* __restrict__ out, int n)
{
    __shared__ float sw[96];
    int tid = threadIdx.x;
    if (tid < 96) sw[tid] = w2[tid];
    __syncthreads();
    int t = blockIdx.x * blockDim.x + tid;
    int pr = t >> 3, sub = t & 7;
    if (pr >= n / 2) return;
    float4 r0, r1;
    gcn_pair((const ulonglong2*)Yf, pr * 2, sub, 0, bias, r0, r1);
    int c = 4 * sub;
    #pragma unroll
    for (int j = 0; j < 2; j++) {
        float4 v = relu4(j == 0 ? r0 : r1);
        float p0 = v.x * sw[(c+0)*3+0] + v.y * sw[(c+1)*3+0] + v.z * sw[(c+2)*3+0] + v.w * sw[(c+3)*3+0];
        float p1 = v.x * sw[(c+0)*3+1] + v.y * sw[(c+1)*3+1] + v.z * sw[(c+2)*3+1] + v.w * sw[(c+3)*3+1];
        float p2 = v.x * sw[(c+0)*3+2] + v.y * sw[(c+1)*3+2] + v.z * sw[(c+2)*3+2] + v.w * sw[(c+3)*3+2];
        #pragma unroll
        for (int off = 4; off; off >>= 1) {
            p0 += __shfl_down_sync(0xffffffffu, p0, off, 8);
            p1 += __shfl_down_sync(0xffffffffu, p1, off, 8);
            p2 += __shfl_down_sync(0xffffffffu, p2, off, 8);
        }
        if (sub == 0) {
            int node = pr * 2 + j;
            out[node * 3 + 0] = p0 + __ldg(&b2[0]);
            out[node * 3 + 1] = p1 + __ldg(&b2[1]);
            out[node * 3 + 2] = p2 + __ldg(&b2[2]);
        }
    }
}

// ---------------------------------------------------------------------------
static inline int ceil_div(int a, int b) { return (a + b - 1) / b; }

extern "C" void kernel_launch(void* const* d_in, const int* in_sizes, int n_in,
                              void* d_out, int out_size) {
    const float* x     = (const float*)d_in[0];
    const float* fc1_w = (const float*)d_in[1];
    const float* fc1_b = (const float*)d_in[2];
    const float* w1 = (const float*)d_in[3];  const float* b1 = (const float*)d_in[4];
    const float* w2 = (const float*)d_in[5];  const float* b2 = (const float*)d_in[6];
    const float* w3 = (const float*)d_in[7];  const float* b3 = (const float*)d_in[8];
    const float* w4 = (const float*)d_in[9];  const float* b4 = (const float*)d_in[10];
    const float* w5 = (const float*)d_in[11]; const float* b5 = (const float*)d_in[12];
    const float* fc2_w = (const float*)d_in[13];
    const float* fc2_b = (const float*)d_in[14];
    const int* ei0 = (const int*)d_in[18];
    const int* ei1 = (const int*)d_in[19];
    const int* ei2 = (const int*)d_in[20];
    float* out = (float*)d_out;

    float4 *Y, *H, *G2, *G4, *G3;
    cudaGetSymbolAddress((void**)&Y,  g_Y);
    cudaGetSymbolAddress((void**)&H,  g_H);
    cudaGetSymbolAddress((void**)&G2, g_G2);
    cudaGetSymbolAddress((void**)&G4, g_G4);
    cudaGetSymbolAddress((void**)&G3, g_G3);

    const int TB = 256;

    // 0-2: start of CSR build
    zero_cnt<<<ceil_div(M, TB), TB>>>();
    hist3<<<ceil_div(ETOT, TB), TB>>>(ei0 + E0, ei1 + E1, ei2 + E2);
    scanA<<<SCAN_NBLK, 256>>>();
    // 3: GCN1 gemm (CSR-independent; profiled launch)
    gemm_fc1<<<ceil_div(N0, 256), TB>>>((const float4*)x, fc1_w, fc1_b, w1, Y, N0);
    // 4-6: rest of CSR build
    scanB<<<1, 512>>>();
    scanC<<<SCAN_NBLK, 256>>>();
    fill3<<<ceil_div(ETOT, TB), TB>>>(ei0, ei1, ei2);

    // 7: GCN1 gather (pair)
    gather<<<ceil_div(N0 * 4, TB), TB>>>(Y, b1, H, N0, 0);

    // 8-9: GCN2
    gemm_down<<<ceil_div(N1, 256), TB>>>(H, w2, Y, N1, NYg / 2, NYg);
    gather<<<ceil_div(N1 * 4, TB), TB>>>(Y, b2, G2, N1, GB1);

    // 10-11: GCN3
    gemm_down<<<ceil_div(N2, 256), TB>>>(G2, w3, Y, N2, NYg / 4, NYg / 2);
    gather<<<ceil_div(N2 * 4, TB), TB>>>(Y, b3, G3, N2, GB2);

    // 12-13: GCN4
    gemm_upadd<<<ceil_div(N1, 256), TB>>>(G2, G3, w4, Y, N1, NYg / 2);
    gather<<<ceil_div(N1 * 4, TB), TB>>>(Y, b4, G4, N1, GB1);

    // 14-15: GCN5 + fc2
    gemm_upadd<<<ceil_div(N0, 256), TB>>>(H, G4, w5, Y, N0, NYg);
    gather_fc2<<<ceil_div(N0 * 4, TB), TB>>>(Y, b5, fc2_w, fc2_b, out, N0);

    (void)in_sizes; (void)n_in; (void)out_size;
}

// round 9
// speedup vs baseline: 1.5433x; 1.1963x over previous
#include <cuda_runtime.h>

// Net_multi_11390253269716: 3-level GCN U-Net, 784x480 grid, C=32.
// R9: R3 build+gather verbatim (proven 248us) + staged-x shared gemm
//     (zero shuffles; MIO ops per node 40 -> 17).

#define NXg 784
#define NYg 480
#define C 32
#define N0 (NXg * NYg)        // 376320
#define N1 (N0 / 4)           // 94080
#define N2 (N0 / 16)          // 23520
#define E0 (4 * N0)
#define E1 (4 * N1)
#define E2 (4 * N2)
#define ETOT (E0 + E1 + E2)   // 1975680
#define M (N0 + N1 + N2)      // 493920
#define GB1 N0
#define GB2 (N0 + N1)
#define SCAN_NBLK ((M + 1023) / 1024)   // 483
#define NPB 128               // nodes per gemm block

typedef unsigned long long ull;

// ---------------- scratch ----------------
__device__ float4 g_Y [N0 * 8];
__device__ float4 g_H [N0 * 8];
__device__ float4 g_G2[N1 * 8];
__device__ float4 g_G4[N1 * 8];
__device__ float4 g_G3[N2 * 8];
__device__ int   g_cnt[M];
__device__ int   g_rowptr[M + 1];
__device__ int   g_eix[ETOT];
__device__ float g_dinv[M];
__device__ int   g_bsum[SCAN_NBLK];

// ---------------- f32x2 helpers ----------------
__device__ __forceinline__ ull pk2(float a, float b) {
    ull r; asm("mov.b64 %0, {%1, %2};" : "=l"(r) : "f"(a), "f"(b)); return r;
}
__device__ __forceinline__ ull fma2_(ull a, ull b, ull c) {
    ull d; asm("fma.rn.f32x2 %0, %1, %2, %3;" : "=l"(d) : "l"(a), "l"(b), "l"(c)); return d;
}
__device__ __forceinline__ float2 up2_(ull v) {
    float2 f; asm("mov.b64 {%0, %1}, %2;" : "=f"(f.x), "=f"(f.y) : "l"(v)); return f;
}
__device__ __forceinline__ float4 relu4(float4 v) {
    v.x = fmaxf(v.x, 0.f); v.y = fmaxf(v.y, 0.f);
    v.z = fmaxf(v.z, 0.f); v.w = fmaxf(v.w, 0.f);
    return v;
}

// ---------------- CSR build (R3-proven, 6 launches) ----------------
__global__ void zero_cnt() {
    int i = blockIdx.x * blockDim.x + threadIdx.x;
    if (i < M) g_cnt[i] = 0;
}

__global__ void hist3(const int* __restrict__ d0, const int* __restrict__ d1,
                      const int* __restrict__ d2) {
    int t = blockIdx.x * blockDim.x + threadIdx.x;
    int g;
    if (t < E0) g = d0[t];
    else if (t < E0 + E1) g = GB1 + d1[t - E0];
    else if (t < ETOT) g = GB2 + d2[t - E0 - E1];
    else return;
    atomicAdd(&g_cnt[g], 1);
}

__global__ void scanA() {
    __shared__ int sb[256];
    int tid = threadIdx.x;
    int base = blockIdx.x * 1024 + tid * 4;
    int v = 0;
    #pragma unroll
    for (int k = 0; k < 4; k++) if (base + k < M) v += g_cnt[base + k];
    sb[tid] = v; __syncthreads();
    for (int off = 128; off; off >>= 1) {
        if (tid < off) sb[tid] += sb[tid + off];
        __syncthreads();
    }
    if (tid == 0) g_bsum[blockIdx.x] = sb[0];
}

__global__ void scanB() {
    __shared__ int sb[512];
    int tid = threadIdx.x;
    int v = (tid < SCAN_NBLK) ? g_bsum[tid] : 0;
    sb[tid] = v; __syncthreads();
    for (int off = 1; off < 512; off <<= 1) {
        int t = (tid >= off) ? sb[tid - off] : 0;
        __syncthreads();
        sb[tid] += t;
        __syncthreads();
    }
    if (tid < SCAN_NBLK) g_bsum[tid] = sb[tid] - v;
}

__global__ void scanC() {
    __shared__ int sb[256];
    int tid = threadIdx.x;
    int base = blockIdx.x * 1024 + tid * 4;
    int v[4], p[4], tsum = 0;
    #pragma unroll
    for (int k = 0; k < 4; k++) {
        v[k] = (base + k < M) ? g_cnt[base + k] : 0;
        p[k] = tsum; tsum += v[k];
    }
    sb[tid] = tsum; __syncthreads();
    for (int off = 1; off < 256; off <<= 1) {
        int t = (tid >= off) ? sb[tid - off] : 0;
        __syncthreads();
        sb[tid] += t;
        __syncthreads();
    }
    int off0 = g_bsum[blockIdx.x] + sb[tid] - tsum;
    #pragma unroll
    for (int k = 0; k < 4; k++) {
        int i = base + k;
        if (i < M) {
            g_rowptr[i] = off0 + p[k];
            g_dinv[i] = rsqrtf((float)v[k] + 1.0f);
            g_cnt[i] = 0;
        }
    }
    if (blockIdx.x == 0 && tid == 0) g_rowptr[M] = ETOT;
}

__global__ void fill3(const int* __restrict__ ei0, const int* __restrict__ ei1,
                      const int* __restrict__ ei2) {
    int t = blockIdx.x * blockDim.x + threadIdx.x;
    int g, s;
    if (t < E0)           { g = ei0[E0 + t];                 s = ei0[t]; }
    else if (t < E0 + E1) { int e = t - E0;      g = GB1 + ei1[E1 + e]; s = ei1[e]; }
    else if (t < ETOT)    { int e = t - E0 - E1; g = GB2 + ei2[E2 + e]; s = ei2[e]; }
    else return;
    int pos = g_rowptr[g] + atomicAdd(&g_cnt[g], 1);
    g_eix[pos] = s;
}

// ---------------- staged-x gemm ----------------
// Block = 256 threads, 128 nodes. x tile staged in shared with 36-float row
// pitch (9 float4) -> the 4 groups of a warp hit distinct bank quads.
// Group i of warp handles local nodes wbase + i + 4j, j=0..3.
#define GEMM_COMPUTE(n_)                                                  \
    __syncthreads();                                                      \
    int lane = tid & 31;                                                  \
    int sub = lane & 7, grp = lane >> 3;                                  \
    int lbase = (tid >> 5) * 16 + grp;                                    \
    ull a01[4] = {0, 0, 0, 0}, a23[4] = {0, 0, 0, 0};                     \
    _Pragma("unroll")                                                     \
    for (int g = 0; g < 8; g++) {                                         \
        ulonglong2 w0 = swu[(4 * g + 0) * 8 + sub];                       \
        ulonglong2 w1 = swu[(4 * g + 1) * 8 + sub];                       \
        ulonglong2 w2 = swu[(4 * g + 2) * 8 + sub];                       \
        ulonglong2 w3 = swu[(4 * g + 3) * 8 + sub];                       \
        _Pragma("unroll")                                                 \
        for (int j = 0; j < 4; j++) {                                     \
            float4 xv = sx[(lbase + 4 * j) * 9 + g];                      \
            a01[j] = fma2_(pk2(xv.x, xv.x), w0.x, a01[j]);                \
            a23[j] = fma2_(pk2(xv.x, xv.x), w0.y, a23[j]);                \
            a01[j] = fma2_(pk2(xv.y, xv.y), w1.x, a01[j]);                \
            a23[j] = fma2_(pk2(xv.y, xv.y), w1.y, a23[j]);                \
            a01[j] = fma2_(pk2(xv.z, xv.z), w2.x, a01[j]);                \
            a23[j] = fma2_(pk2(xv.z, xv.z), w2.y, a23[j]);                \
            a01[j] = fma2_(pk2(xv.w, xv.w), w3.x, a01[j]);                \
            a23[j] = fma2_(pk2(xv.w, xv.w), w3.y, a23[j]);                \
        }                                                                 \
    }                                                                     \
    _Pragma("unroll")                                                     \
    for (int j = 0; j < 4; j++) {                                         \
        int node = blockIdx.x * NPB + lbase + 4 * j;                      \
        if (node < n_) {                                                  \
            ulonglong2 r; r.x = a01[j]; r.y = a23[j];                     \
            ((ulonglong2*)Y)[node * 8 + sub] = r;                        \
        }                                                                 \
    }

__global__ void __launch_bounds__(256)
gemm_fc1(const float4* __restrict__ x,
         const float* __restrict__ fc1w, const float* __restrict__ fc1b,
         const float* __restrict__ w, float4* __restrict__ Y, int n)
{
    __shared__ ulonglong2 swu[256];
    __shared__ float4 sx[NPB * 9];
    __shared__ float4 sfw[32];
    __shared__ float4 sfb[8];
    int tid = threadIdx.x;
    swu[tid] = ((const ulonglong2*)w)[tid];
    if (tid < 32) sfw[tid] = ((const float4*)fc1w)[tid];
    if (tid < 8)  sfb[tid] = ((const float4*)fc1b)[tid];
    __syncthreads();
    // stage: thread pair per node; each stages 4 channel-quads
    int ln = tid >> 1;
    int nd = blockIdx.x * NPB + ln;
    int half = (tid & 1) * 4;
    if (nd < n) {
        float4 xin = x[nd];
        #pragma unroll
        for (int i = 0; i < 4; i++) {
            int q = half + i;
            float4 h = sfb[q];
            float4 r0 = sfw[q], r1 = sfw[8 + q], r2 = sfw[16 + q], r3 = sfw[24 + q];
            h.x += xin.x * r0.x + xin.y * r1.x + xin.z * r2.x + xin.w * r3.x;
            h.y += xin.x * r0.y + xin.y * r1.y + xin.z * r2.y + xin.w * r3.y;
            h.z += xin.x * r0.z + xin.y * r1.z + xin.z * r2.z + xin.w * r3.z;
            h.w += xin.x * r0.w + xin.y * r1.w + xin.z * r2.w + xin.w * r3.w;
            sx[ln * 9 + q] = relu4(h);
        }
    }
    GEMM_COMPUTE(n)
}

__global__ void __launch_bounds__(256)
gemm_down(const float4* __restrict__ in, const float* __restrict__ w,
          float4* __restrict__ Y, int n, int hy, int win)
{
    __shared__ ulonglong2 swu[256];
    __shared__ float4 sx[NPB * 9];
    int tid = threadIdx.x;
    swu[tid] = ((const ulonglong2*)w)[tid];
    int ln = tid >> 1;
    int nd = blockIdx.x * NPB + ln;
    int half = (tid & 1) * 4;
    if (nd < n) {
        int ix = nd / hy, iy = nd - ix * hy;
        const float4* src = in + ((2 * ix) * win + 2 * iy) * 8 + half;
        #pragma unroll
        for (int i = 0; i < 4; i++)
            sx[ln * 9 + half + i] = relu4(src[i]);
    }
    GEMM_COMPUTE(n)
}

__global__ void __launch_bounds__(256)
gemm_upadd(const float4* __restrict__ base, const float4* __restrict__ coarse,
           const float* __restrict__ w, float4* __restrict__ Y, int n, int hy)
{
    __shared__ ulonglong2 swu[256];
    __shared__ float4 sx[NPB * 9];
    int tid = threadIdx.x;
    swu[tid] = ((const ulonglong2*)w)[tid];
    int ln = tid >> 1;
    int nd = blockIdx.x * NPB + ln;
    int half = (tid & 1) * 4;
    if (nd < n) {
        int ix = nd / hy, iy = nd - ix * hy;
        int cn = (ix >> 1) * (hy >> 1) + (iy >> 1);
        const float4* bsrc = base + nd * 8 + half;
        const float4* csrc = coarse + cn * 8 + half;
        #pragma unroll
        for (int i = 0; i < 4; i++) {
            float4 xb = relu4(bsrc[i]);
            float4 xc = relu4(csrc[i]);
            sx[ln * 9 + half + i] =
                make_float4(xb.x + xc.x, xb.y + xc.y, xb.z + xc.z, xb.w + xc.w);
        }
    }
    GEMM_COMPUTE(n)
}

// ---------------- gather (R3 verbatim) ----------------
__device__ __forceinline__ void gather_acc(
    const ulonglong2* __restrict__ Y, int node, int sub, int gbase,
    const float* __restrict__ bias, ull& a01, ull& a23)
{
    float di = g_dinv[gbase + node];
    int beg = g_rowptr[gbase + node];
    int end = g_rowptr[gbase + node + 1];
    float4 bb = ((const float4*)bias)[sub];
    float s2 = di * di;
    ulonglong2 y = Y[node * 8 + sub];
    ull s22 = pk2(s2, s2);
    a01 = fma2_(y.x, s22, pk2(bb.x, bb.y));
    a23 = fma2_(y.y, s22, pk2(bb.z, bb.w));
    for (int p = beg; p < end; p++) {
        int s = g_eix[p];
        float nm = g_dinv[gbase + s] * di;
        ulonglong2 v = Y[s * 8 + sub];
        ull nn = pk2(nm, nm);
        a01 = fma2_(v.x, nn, a01);
        a23 = fma2_(v.y, nn, a23);
    }
}

__global__ void gather(const float4* __restrict__ Yf,
                       const float* __restrict__ bias,
                       float4* __restrict__ OUT, int n, int gbase)
{
    int t = blockIdx.x * blockDim.x + threadIdx.x;
    int node = t >> 3, sub = t & 7;
    if (node >= n) return;
    ull a01, a23;
    gather_acc((const ulonglong2*)Yf, node, sub, gbase, bias, a01, a23);
    ulonglong2 r; r.x = a01; r.y = a23;
    ((ulonglong2*)OUT)[node * 8 + sub] = r;
}

__global__ void gather_fc2(const float4* __restrict__ Yf,
                           const float* __restrict__ bias,
                           const float* __restrict__ w2, const float* __restrict__ b2,
                           float* __restrict__ out, int n)
{
    __shared__ float sw[96];
    int tid = threadIdx.x;
    if (tid < 96) sw[tid] = w2[tid];
    __syncthreads();
    int t = blockIdx.x * blockDim.x + tid;
    int node = t >> 3, sub = t & 7;
    if (node >= n) return;
    ull a01, a23;
    gather_acc((const ulonglong2*)Yf, node, sub, 0, bias, a01, a23);
    float2 v01 = up2_(a01), v23 = up2_(a23);
    float4 v = relu4(make_float4(v01.x, v01.y, v23.x, v23.y));
    int c = 4 * sub;
    float p0 = v.x * sw[(c+0)*3+0] + v.y * sw[(c+1)*3+0] + v.z * sw[(c+2)*3+0] + v.w * sw[(c+3)*3+0];
    float p1 = v.x * sw[(c+0)*3+1] + v.y * sw[(c+1)*3+1] + v.z * sw[(c+2)*3+1] + v.w * sw[(c+3)*3+1];
    float p2 = v.x * sw[(c+0)*3+2] + v.y * sw[(c+1)*3+2] + v.z * sw[(c+2)*3+2] + v.w * sw[(c+3)*3+2];
    #pragma unroll
    for (int off = 4; off; off >>= 1) {
        p0 += __shfl_down_sync(0xffffffffu, p0, off, 8);
        p1 += __shfl_down_sync(0xffffffffu, p1, off, 8);
        p2 += __shfl_down_sync(0xffffffffu, p2, off, 8);
    }
    if (sub == 0) {
        out[node * 3 + 0] = p0 + __ldg(&b2[0]);
        out[node * 3 + 1] = p1 + __ldg(&b2[1]);
        out[node * 3 + 2] = p2 + __ldg(&b2[2]);
    }
}

// ---------------------------------------------------------------------------
static inline int ceil_div(int a, int b) { return (a + b - 1) / b; }

extern "C" void kernel_launch(void* const* d_in, const int* in_sizes, int n_in,
                              void* d_out, int out_size) {
    const float* x     = (const float*)d_in[0];
    const float* fc1_w = (const float*)d_in[1];
    const float* fc1_b = (const float*)d_in[2];
    const float* w1 = (const float*)d_in[3];  const float* b1 = (const float*)d_in[4];
    const float* w2 = (const float*)d_in[5];  const float* b2 = (const float*)d_in[6];
    const float* w3 = (const float*)d_in[7];  const float* b3 = (const float*)d_in[8];
    const float* w4 = (const float*)d_in[9];  const float* b4 = (const float*)d_in[10];
    const float* w5 = (const float*)d_in[11]; const float* b5 = (const float*)d_in[12];
    const float* fc2_w = (const float*)d_in[13];
    const float* fc2_b = (const float*)d_in[14];
    const int* ei0 = (const int*)d_in[18];
    const int* ei1 = (const int*)d_in[19];
    const int* ei2 = (const int*)d_in[20];
    float* out = (float*)d_out;

    float4 *Y, *H, *G2, *G4, *G3;
    cudaGetSymbolAddress((void**)&Y,  g_Y);
    cudaGetSymbolAddress((void**)&H,  g_H);
    cudaGetSymbolAddress((void**)&G2, g_G2);
    cudaGetSymbolAddress((void**)&G4, g_G4);
    cudaGetSymbolAddress((void**)&G3, g_G3);

    const int TB = 256;

    // 0-2: start of CSR build
    zero_cnt<<<ceil_div(M, TB), TB>>>();
    hist3<<<ceil_div(ETOT, TB), TB>>>(ei0 + E0, ei1 + E1, ei2 + E2);
    scanA<<<SCAN_NBLK, 256>>>();
    // 3: GCN1 gemm (CSR-independent; profiled launch)
    gemm_fc1<<<ceil_div(N0, NPB), TB>>>((const float4*)x, fc1_w, fc1_b, w1, Y, N0);
    // 4-6: rest of CSR build
    scanB<<<1, 512>>>();
    scanC<<<SCAN_NBLK, 256>>>();
    fill3<<<ceil_div(ETOT, TB), TB>>>(ei0, ei1, ei2);

    // 7: GCN1 gather
    gather<<<N0 / 32, TB>>>(Y, b1, H, N0, 0);

    // 8-9: GCN2
    gemm_down<<<ceil_div(N1, NPB), TB>>>(H, w2, Y, N1, NYg / 2, NYg);
    gather<<<N1 / 32, TB>>>(Y, b2, G2, N1, GB1);

    // 10-11: GCN3
    gemm_down<<<ceil_div(N2, NPB), TB>>>(G2, w3, Y, N2, NYg / 4, NYg / 2);
    gather<<<N2 / 32, TB>>>(Y, b3, G3, N2, GB2);

    // 12-13: GCN4
    gemm_upadd<<<ceil_div(N1, NPB), TB>>>(G2, G3, w4, Y, N1, NYg / 2);
    gather<<<N1 / 32, TB>>>(Y, b4, G4, N1, GB1);

    // 14-15: GCN5 + fc2
    gemm_upadd<<<ceil_div(N0, NPB), TB>>>(H, G4, w5, Y, N0, NYg);
    gather_fc2<<<N0 / 32, TB>>>(Y, b5, fc2_w, fc2_b, out, N0);

    (void)in_sizes; (void)n_in; (void)out_size;
}